// round 1
// baseline (speedup 1.0000x reference)
#include <cuda_runtime.h>
#include <math.h>

#define T   2048
#define H   1024
#define FF  3584
#define NE  8
#define TK  2
#define NSLOT (T*TK)

// ---- scratch (device globals; no runtime allocation allowed) ----
__device__ float d_act[(size_t)NSLOT * FF];   // 58.7 MB: silu(gate)*up, pre-scaled by routing weight
__device__ float d_y[(size_t)NSLOT * H];      // 16.7 MB: per-slot down-proj output
__device__ int   d_slot_token[NSLOT];
__device__ float d_slot_w[NSLOT];
__device__ int   d_token_slot[NSLOT];
__device__ int   d_topk_e[NSLOT];
__device__ float d_topk_w[NSLOT];
__device__ int   d_counts[NE];
__device__ int   d_offsets[NE];
__device__ int   d_cursor[NE];

// ---------------------------------------------------------------------------
__global__ void zero_counts_kernel() {
    if (threadIdx.x < NE) d_counts[threadIdx.x] = 0;
}

// One warp per token: logits = x @ gate_w^T, softmax->top2->renorm.
__global__ void router_kernel(const float* __restrict__ x,
                              const float* __restrict__ gw,
                              float* __restrict__ logits, int write_logits)
{
    int warp = (blockIdx.x * blockDim.x + threadIdx.x) >> 5;
    int lane = threadIdx.x & 31;
    if (warp >= T) return;
    const float* xr = x + (size_t)warp * H;

    float acc[NE];
#pragma unroll
    for (int e = 0; e < NE; e++) acc[e] = 0.f;
    for (int i = lane; i < H; i += 32) {
        float xv = xr[i];
#pragma unroll
        for (int e = 0; e < NE; e++) acc[e] += xv * gw[e * H + i];
    }
#pragma unroll
    for (int e = 0; e < NE; e++) {
#pragma unroll
        for (int off = 16; off > 0; off >>= 1)
            acc[e] += __shfl_xor_sync(0xffffffffu, acc[e], off);
    }
    if (lane == 0) {
        if (write_logits) {
#pragma unroll
            for (int e = 0; e < NE; e++) logits[warp * NE + e] = acc[e];
        }
        // top-2 by logit (== top-2 by prob), first-occurrence tie-break
        int i0 = 0;
#pragma unroll
        for (int e = 1; e < NE; e++) if (acc[e] > acc[i0]) i0 = e;
        int i1 = (i0 == 0) ? 1 : 0;
#pragma unroll
        for (int e = 0; e < NE; e++)
            if (e != i0 && acc[e] > acc[i1]) i1 = e;
        // renormalized top-2 probs == softmax over the two top logits
        float m  = fmaxf(acc[i0], acc[i1]);
        float p0 = expf(acc[i0] - m), p1 = expf(acc[i1] - m);
        float inv = 1.f / (p0 + p1);
        d_topk_e[warp * 2 + 0] = i0;  d_topk_w[warp * 2 + 0] = p0 * inv;
        d_topk_e[warp * 2 + 1] = i1;  d_topk_w[warp * 2 + 1] = p1 * inv;
        atomicAdd(&d_counts[i0], 1);
        atomicAdd(&d_counts[i1], 1);
    }
}

__global__ void scan_kernel() {
    int off = 0;
    for (int e = 0; e < NE; e++) {
        d_offsets[e] = off;
        off += d_counts[e];
        d_cursor[e] = 0;
    }
}

__global__ void scatter_kernel() {
    int t = blockIdx.x * blockDim.x + threadIdx.x;
    if (t >= T) return;
#pragma unroll
    for (int k = 0; k < TK; k++) {
        int e   = d_topk_e[t * 2 + k];
        int pos = d_offsets[e] + atomicAdd(&d_cursor[e], 1);
        d_slot_token[pos]    = t;
        d_slot_w[pos]        = d_topk_w[t * 2 + k];
        d_token_slot[t * 2 + k] = pos;
    }
}

// ---------------------------------------------------------------------------
// GEMM1: act[slot, n] = silu(x@Wg)[n] * (x@Wu)[n] * routing_w
// 64x64 output tile, BK=16, 256 threads, dual accumulators sharing A tile.
// grid = (m_tile=32, n_tile=56, expert=8); m fastest -> B strip reuse in L2.
__global__ __launch_bounds__(256) void gemm1_kernel(const float* __restrict__ x,
                                                    const float* __restrict__ wgu)
{
    int e   = blockIdx.z;
    int cnt = d_counts[e];
    int m0  = blockIdx.x * 64;
    if (m0 >= cnt) return;
    int seg = d_offsets[e];
    int n0  = blockIdx.y * 64;

    __shared__ float As[16][64];
    __shared__ float Bg[16][64];
    __shared__ float Bu[16][64];

    int tid = threadIdx.x;
    int ar  = tid >> 2;          // 0..63 : A row
    int ak  = (tid & 3) * 4;     // k sub-offset (float4)
    bool arow_ok = (m0 + ar) < cnt;
    int tok = arow_ok ? d_slot_token[seg + m0 + ar] : -1;
    const float* xrow = x + (size_t)(tok < 0 ? 0 : tok) * H;

    int bn  = tid & 63;
    int bk0 = tid >> 6;          // 0..3
    const float* wbase = wgu + (size_t)e * H * (2 * FF);

    float accg[4][4], accu[4][4];
#pragma unroll
    for (int i = 0; i < 4; i++)
#pragma unroll
        for (int j = 0; j < 4; j++) { accg[i][j] = 0.f; accu[i][j] = 0.f; }

    int tx = tid & 15, ty = tid >> 4;

    for (int k0 = 0; k0 < H; k0 += 16) {
        float4 av = make_float4(0.f, 0.f, 0.f, 0.f);
        if (tok >= 0) av = *(const float4*)(xrow + k0 + ak);
        As[ak + 0][ar] = av.x;  As[ak + 1][ar] = av.y;
        As[ak + 2][ar] = av.z;  As[ak + 3][ar] = av.w;
#pragma unroll
        for (int i = 0; i < 4; i++) {
            int kk = bk0 * 4 + i;
            const float* wr = wbase + (size_t)(k0 + kk) * (2 * FF) + n0 + bn;
            Bg[kk][bn] = wr[0];
            Bu[kk][bn] = wr[FF];
        }
        __syncthreads();
#pragma unroll
        for (int kk = 0; kk < 16; kk++) {
            float4 a4 = *(const float4*)&As[kk][ty * 4];
            float4 g4 = *(const float4*)&Bg[kk][tx * 4];
            float4 u4 = *(const float4*)&Bu[kk][tx * 4];
            float aa[4] = {a4.x, a4.y, a4.z, a4.w};
            float gg[4] = {g4.x, g4.y, g4.z, g4.w};
            float uu[4] = {u4.x, u4.y, u4.z, u4.w};
#pragma unroll
            for (int i = 0; i < 4; i++)
#pragma unroll
                for (int j = 0; j < 4; j++) {
                    accg[i][j] += aa[i] * gg[j];
                    accu[i][j] += aa[i] * uu[j];
                }
        }
        __syncthreads();
    }

#pragma unroll
    for (int i = 0; i < 4; i++) {
        int m = m0 + ty * 4 + i;
        if (m < cnt) {
            int slot = seg + m;
            float w  = d_slot_w[slot];
            float* orow = d_act + (size_t)slot * FF + n0 + tx * 4;
#pragma unroll
            for (int j = 0; j < 4; j++) {
                float g = accg[i][j], u = accu[i][j];
                float s = g / (1.f + expf(-g));   // silu
                orow[j] = s * u * w;
            }
        }
    }
}

// ---------------------------------------------------------------------------
// GEMM2: y[slot, n] = act[slot, :] @ w_down[e]   (routing weight already baked in)
// grid = (m_tile=32, n_tile=16, expert=8)
__global__ __launch_bounds__(256) void gemm2_kernel(const float* __restrict__ wdn)
{
    int e   = blockIdx.z;
    int cnt = d_counts[e];
    int m0  = blockIdx.x * 64;
    if (m0 >= cnt) return;
    int seg = d_offsets[e];
    int n0  = blockIdx.y * 64;

    __shared__ float As[16][64];
    __shared__ float Bs[16][64];

    int tid = threadIdx.x;
    int ar  = tid >> 2;
    int ak  = (tid & 3) * 4;
    bool arow_ok = (m0 + ar) < cnt;
    const float* arow = d_act + (size_t)(seg + m0 + (arow_ok ? ar : 0)) * FF;

    int bn  = tid & 63;
    int bk0 = tid >> 6;
    const float* wbase = wdn + (size_t)e * FF * H;

    float acc[4][4];
#pragma unroll
    for (int i = 0; i < 4; i++)
#pragma unroll
        for (int j = 0; j < 4; j++) acc[i][j] = 0.f;

    int tx = tid & 15, ty = tid >> 4;

    for (int k0 = 0; k0 < FF; k0 += 16) {
        float4 av = make_float4(0.f, 0.f, 0.f, 0.f);
        if (arow_ok) av = *(const float4*)(arow + k0 + ak);
        As[ak + 0][ar] = av.x;  As[ak + 1][ar] = av.y;
        As[ak + 2][ar] = av.z;  As[ak + 3][ar] = av.w;
#pragma unroll
        for (int i = 0; i < 4; i++) {
            int kk = bk0 * 4 + i;
            Bs[kk][bn] = wbase[(size_t)(k0 + kk) * H + n0 + bn];
        }
        __syncthreads();
#pragma unroll
        for (int kk = 0; kk < 16; kk++) {
            float4 a4 = *(const float4*)&As[kk][ty * 4];
            float4 b4 = *(const float4*)&Bs[kk][tx * 4];
            float aa[4] = {a4.x, a4.y, a4.z, a4.w};
            float bb[4] = {b4.x, b4.y, b4.z, b4.w};
#pragma unroll
            for (int i = 0; i < 4; i++)
#pragma unroll
                for (int j = 0; j < 4; j++)
                    acc[i][j] += aa[i] * bb[j];
        }
        __syncthreads();
    }

#pragma unroll
    for (int i = 0; i < 4; i++) {
        int m = m0 + ty * 4 + i;
        if (m < cnt) {
            int slot = seg + m;
            float* yr = d_y + (size_t)slot * H + n0 + tx * 4;
#pragma unroll
            for (int j = 0; j < 4; j++) yr[j] = acc[i][j];
        }
    }
}

// out[t, n] = y[slot0(t), n] + y[slot1(t), n]
__global__ void combine_kernel(float* __restrict__ out)
{
    int idx = blockIdx.x * blockDim.x + threadIdx.x;
    if (idx >= T * H) return;
    int t = idx >> 10;          // H == 1024
    int n = idx & (H - 1);
    int s0 = d_token_slot[t * 2 + 0];
    int s1 = d_token_slot[t * 2 + 1];
    out[idx] = d_y[(size_t)s0 * H + n] + d_y[(size_t)s1 * H + n];
}

// ---------------------------------------------------------------------------
extern "C" void kernel_launch(void* const* d_in, const int* in_sizes, int n_in,
                              void* d_out, int out_size)
{
    const float* x   = (const float*)d_in[0];   // [2,1024,1024]
    const float* gw  = (const float*)d_in[1];   // [8,1024]
    const float* wgu = (const float*)d_in[2];   // [8,1024,7168]
    const float* wdn = (const float*)d_in[3];   // [8,3584,1024]
    float* out = (float*)d_out;

    int write_logits = (out_size >= T * H + T * NE) ? 1 : 0;
    float* logits = out + (size_t)T * H;

    zero_counts_kernel<<<1, 32>>>();
    router_kernel<<<(T * 32 + 255) / 256, 256>>>(x, gw, logits, write_logits);
    scan_kernel<<<1, 1>>>();
    scatter_kernel<<<(T + 255) / 256, 256>>>();
    gemm1_kernel<<<dim3(32, FF / 64, NE), 256>>>(x, wgu);        // (32, 56, 8)
    gemm2_kernel<<<dim3(32, H / 64, NE), 256>>>(wdn);            // (32, 16, 8)
    combine_kernel<<<(T * H + 255) / 256, 256>>>(out);
}

// round 3
// speedup vs baseline: 2.2849x; 2.2849x over previous
#include <cuda_runtime.h>
#include <math.h>
#include <stdint.h>

#define T   2048
#define H   1024
#define FF  3584
#define NE  8
#define TK  2
#define NSLOT (T*TK)

#define BM  128
#define BK  32
#define SMEMSZ 65536

// ---- scratch (device globals; no runtime allocation allowed) ----
__device__ __align__(16) float d_act[(size_t)(NSLOT + BM) * FF];
__device__ __align__(16) float d_y[(size_t)NSLOT * H];
__device__ int   d_slot_token[NSLOT];
__device__ float d_slot_w[NSLOT];
__device__ int   d_token_slot[NSLOT];
__device__ int   d_topk_e[NSLOT];
__device__ float d_topk_w[NSLOT];
__device__ int   d_counts[NE];
__device__ int   d_offsets[NE];
__device__ int   d_cursor[NE];

// ===================== helpers =====================
__device__ __forceinline__ uint32_t f2tf(float f) {
    uint32_t r;
    asm("cvt.rna.tf32.f32 %0, %1;" : "=r"(r) : "f"(f));
    return r;
}
// 128B-row XOR swizzle on byte offsets (rows are 32 floats = 128 B)
__device__ __forceinline__ uint32_t SWZ(uint32_t b) {
    return b ^ ((b >> 3) & 0x70);
}

__device__ __forceinline__ void mma_tf32(float* c, const uint32_t* a, const uint32_t* b) {
    asm volatile(
        "mma.sync.aligned.m16n8k8.row.col.f32.tf32.tf32.f32 "
        "{%0,%1,%2,%3}, {%4,%5,%6,%7}, {%8,%9}, {%0,%1,%2,%3};\n"
        : "+f"(c[0]), "+f"(c[1]), "+f"(c[2]), "+f"(c[3])
        : "r"(a[0]), "r"(a[1]), "r"(a[2]), "r"(a[3]), "r"(b[0]), "r"(b[1]));
}

// ===================== small kernels =====================
__global__ void zero_counts_kernel() {
    if (threadIdx.x < NE) d_counts[threadIdx.x] = 0;
}

__global__ void router_kernel(const float* __restrict__ x,
                              const float* __restrict__ gw,
                              float* __restrict__ logits, int write_logits)
{
    int warp = (blockIdx.x * blockDim.x + threadIdx.x) >> 5;
    int lane = threadIdx.x & 31;
    if (warp >= T) return;
    const float* xr = x + (size_t)warp * H;

    float acc[NE];
#pragma unroll
    for (int e = 0; e < NE; e++) acc[e] = 0.f;
    for (int i = lane; i < H; i += 32) {
        float xv = xr[i];
#pragma unroll
        for (int e = 0; e < NE; e++) acc[e] += xv * gw[e * H + i];
    }
#pragma unroll
    for (int e = 0; e < NE; e++) {
#pragma unroll
        for (int off = 16; off > 0; off >>= 1)
            acc[e] += __shfl_xor_sync(0xffffffffu, acc[e], off);
    }
    if (lane == 0) {
        if (write_logits) {
#pragma unroll
            for (int e = 0; e < NE; e++) logits[warp * NE + e] = acc[e];
        }
        int i0 = 0;
#pragma unroll
        for (int e = 1; e < NE; e++) if (acc[e] > acc[i0]) i0 = e;
        int i1 = (i0 == 0) ? 1 : 0;
#pragma unroll
        for (int e = 0; e < NE; e++)
            if (e != i0 && acc[e] > acc[i1]) i1 = e;
        float m  = fmaxf(acc[i0], acc[i1]);
        float p0 = expf(acc[i0] - m), p1 = expf(acc[i1] - m);
        float inv = 1.f / (p0 + p1);
        d_topk_e[warp * 2 + 0] = i0;  d_topk_w[warp * 2 + 0] = p0 * inv;
        d_topk_e[warp * 2 + 1] = i1;  d_topk_w[warp * 2 + 1] = p1 * inv;
        atomicAdd(&d_counts[i0], 1);
        atomicAdd(&d_counts[i1], 1);
    }
}

__global__ void scan_kernel() {
    int off = 0;
    for (int e = 0; e < NE; e++) {
        d_offsets[e] = off;
        off += d_counts[e];
        d_cursor[e] = 0;
    }
}

__global__ void scatter_kernel() {
    int t = blockIdx.x * blockDim.x + threadIdx.x;
    if (t >= T) return;
#pragma unroll
    for (int k = 0; k < TK; k++) {
        int e   = d_topk_e[t * 2 + k];
        int pos = d_offsets[e] + atomicAdd(&d_cursor[e], 1);
        d_slot_token[pos]       = t;
        d_slot_w[pos]           = d_topk_w[t * 2 + k];
        d_token_slot[t * 2 + k] = pos;
    }
}

// ===================== mma.sync tf32 grouped GEMM =====================
// IS1:  A = gathered x rows [K=H],  B = w_gate_up [H, 2FF], block tile 128m x 64f
//       dual accumulators (gate & up) share A frags; epilogue silu(g)*u*w -> d_act
// !IS1: A = d_act rows [K=FF], B = w_down [FF, H], block tile 128m x 128n -> d_y
//
// SMEM per stage: A[128][32] tf32 (16KB) + B tiles (16KB) = 32KB; 2 stages.
template <int KTOT, bool IS1>
__global__ __launch_bounds__(256)
void moe_gemm_mma(const float* __restrict__ Aglob, const float* __restrict__ W)
{
    constexpr int NB = IS1 ? (2 * FF) : H;
    constexpr int NI = KTOT / BK;
    constexpr int STAGE = 32768;

    int e   = blockIdx.z;
    int cnt = d_counts[e];
    int m0  = blockIdx.x * BM;
    if (m0 >= cnt) return;
    int seg = d_offsets[e];

    extern __shared__ __align__(16) char smem[];

    int t = threadIdx.x, w = t >> 5, lane = t & 31;
    int g = lane >> 2, tig = lane & 3;

    // ---------- staging setup ----------
    // A: thread (r = t>>1) owns row r, half h = t&1 (16 consecutive k)
    int ar = t >> 1, ah = t & 1;
    const float* asrc;
    if (IS1) {
        int mrow = m0 + ar;
        int tok  = (mrow < cnt) ? d_slot_token[seg + mrow] : 0;
        asrc = Aglob + (size_t)tok * KTOT + ah * 16;
    } else {
        asrc = d_act + (size_t)(seg + m0 + ar) * KTOT + ah * 16;
    }
    uint32_t aoff[4];
#pragma unroll
    for (int q = 0; q < 4; q++) aoff[q] = SWZ((uint32_t)(ar * 128 + ah * 64 + q * 16));

    // B: IS1: set = t>>7 (gate/up), h2 = (t>>6)&1, nl = t&63  (16 k each)
    //    !IS1: nl = t&127, h2 = t>>7                          (16 k each)
    int bset = IS1 ? (t >> 7) : 0;
    int bh   = IS1 ? ((t >> 6) & 1) : (t >> 7);
    int bnl  = IS1 ? (t & 63) : (t & 127);
    int gn;
    if (IS1) gn = bset * FF + blockIdx.y * 64 + bnl;
    else     gn = blockIdx.y * 128 + bnl;
    const float* bsrc = W + (size_t)e * KTOT * NB + gn;
    // B smem: [n][k] rows of 128B; gate at 16384, up at 24576 (IS1); B at 16384 (!IS1)
    uint32_t bbase = IS1 ? (16384u + (uint32_t)bset * 8192u) : 16384u;
    uint32_t boff[4];
#pragma unroll
    for (int q = 0; q < 4; q++)
        boff[q] = bbase + SWZ((uint32_t)(bnl * 128 + bh * 64 + q * 16));

    // ---------- compute setup ----------
    constexpr int MT = IS1 ? 2 : 4;       // m16 tiles per warp
    constexpr int NSETS = IS1 ? 2 : 1;
    int mw = IS1 ? (w >> 1) : (w >> 2);   // warp m index
    int nw = IS1 ? (w & 1)  : (w & 3);    // warp n index
    int mwbase = mw * (IS1 ? 32 : 64);
    int nwbase = nw * 32;

    float acc[NSETS][MT][4][4];
#pragma unroll
    for (int s = 0; s < NSETS; s++)
#pragma unroll
        for (int mt = 0; mt < MT; mt++)
#pragma unroll
            for (int nt = 0; nt < 4; nt++)
#pragma unroll
                for (int q = 0; q < 4; q++) acc[s][mt][nt][q] = 0.f;

    // ---------- mainloop: double-buffered, single sync per iter ----------
    float4 av[4];
    float  bv[16];
#pragma unroll
    for (int q = 0; q < 4; q++) av[q] = __ldg((const float4*)(asrc + q * 4));
#pragma unroll
    for (int kk = 0; kk < 16; kk++) bv[kk] = __ldg(bsrc + (size_t)(bh * 16 + kk) * NB);

    for (int it = 0; it < NI; it++) {
        uint32_t sb = (it & 1) ? STAGE : 0u;
        char* sm = smem + sb;
        // store current regs (convert to tf32)
#pragma unroll
        for (int q = 0; q < 4; q++) {
            uint4 c = make_uint4(f2tf(av[q].x), f2tf(av[q].y), f2tf(av[q].z), f2tf(av[q].w));
            *(uint4*)(sm + aoff[q]) = c;
        }
#pragma unroll
        for (int q = 0; q < 4; q++) {
            uint4 c = make_uint4(f2tf(bv[q * 4 + 0]), f2tf(bv[q * 4 + 1]),
                                 f2tf(bv[q * 4 + 2]), f2tf(bv[q * 4 + 3]));
            *(uint4*)(sm + boff[q]) = c;
        }
        __syncthreads();
        // prefetch next chunk
        if (it + 1 < NI) {
            int k0 = (it + 1) * BK;
#pragma unroll
            for (int q = 0; q < 4; q++)
                av[q] = __ldg((const float4*)(asrc + k0 + q * 4));
#pragma unroll
            for (int kk = 0; kk < 16; kk++)
                bv[kk] = __ldg(bsrc + (size_t)(k0 + bh * 16 + kk) * NB);
        }
        // compute from this buffer
        const char* sA = smem + sb;
        const char* sB = smem + sb + 16384;
#pragma unroll
        for (int ks = 0; ks < 4; ks++) {
            int kc = ks * 8;
            uint32_t afr[MT][4];
#pragma unroll
            for (int mt = 0; mt < MT; mt++) {
                uint32_t rb = (uint32_t)(mwbase + mt * 16 + g) * 128u;
                uint32_t rb8 = rb + 8u * 128u;
                uint32_t c0 = (uint32_t)(kc + tig) * 4u, c1 = c0 + 16u;
                afr[mt][0] = *(const uint32_t*)(sA + SWZ(rb + c0));
                afr[mt][1] = *(const uint32_t*)(sA + SWZ(rb8 + c0));
                afr[mt][2] = *(const uint32_t*)(sA + SWZ(rb + c1));
                afr[mt][3] = *(const uint32_t*)(sA + SWZ(rb8 + c1));
            }
#pragma unroll
            for (int s = 0; s < NSETS; s++) {
                const char* sBs = sB + s * 8192;
#pragma unroll
                for (int nt = 0; nt < 4; nt++) {
                    uint32_t rb = (uint32_t)(nwbase + nt * 8 + g) * 128u;
                    uint32_t c0 = (uint32_t)(kc + tig) * 4u;
                    uint32_t bfr[2];
                    bfr[0] = *(const uint32_t*)(sBs + SWZ(rb + c0));
                    bfr[1] = *(const uint32_t*)(sBs + SWZ(rb + c0 + 16u));
#pragma unroll
                    for (int mt = 0; mt < MT; mt++)
                        mma_tf32(acc[s][mt][nt], afr[mt], bfr);
                }
            }
        }
    }

    // ---------- epilogue ----------
    if (IS1) {
        int n0 = blockIdx.y * 64;
#pragma unroll
        for (int mt = 0; mt < MT; mt++) {
#pragma unroll
            for (int rs = 0; rs < 2; rs++) {
                int m = m0 + mwbase + mt * 16 + g + rs * 8;
                if (m < cnt) {
                    int slot = seg + m;
                    float wgt = d_slot_w[slot];
                    float* row = d_act + (size_t)slot * FF + n0 + nwbase;
#pragma unroll
                    for (int nt = 0; nt < 4; nt++) {
                        float gv0 = acc[0][mt][nt][rs * 2 + 0];
                        float gv1 = acc[0][mt][nt][rs * 2 + 1];
                        float uv0 = acc[1][mt][nt][rs * 2 + 0];
                        float uv1 = acc[1][mt][nt][rs * 2 + 1];
                        float2 o;
                        o.x = gv0 / (1.f + expf(-gv0)) * uv0 * wgt;
                        o.y = gv1 / (1.f + expf(-gv1)) * uv1 * wgt;
                        *(float2*)(row + nt * 8 + 2 * tig) = o;
                    }
                }
            }
        }
    } else {
        int n0 = blockIdx.y * 128;
#pragma unroll
        for (int mt = 0; mt < MT; mt++) {
#pragma unroll
            for (int rs = 0; rs < 2; rs++) {
                int m = m0 + mwbase + mt * 16 + g + rs * 8;
                if (m < cnt) {
                    int slot = seg + m;
                    float* row = d_y + (size_t)slot * H + n0 + nwbase;
#pragma unroll
                    for (int nt = 0; nt < 4; nt++) {
                        float2 o;
                        o.x = acc[0][mt][nt][rs * 2 + 0];
                        o.y = acc[0][mt][nt][rs * 2 + 1];
                        *(float2*)(row + nt * 8 + 2 * tig) = o;
                    }
                }
            }
        }
    }
}

// out[t, n] = y[slot0(t), n] + y[slot1(t), n]
__global__ void combine_kernel(float* __restrict__ out)
{
    int idx = blockIdx.x * blockDim.x + threadIdx.x;
    if (idx >= T * H) return;
    int t = idx >> 10;
    int n = idx & (H - 1);
    int s0 = d_token_slot[t * 2 + 0];
    int s1 = d_token_slot[t * 2 + 1];
    out[idx] = d_y[(size_t)s0 * H + n] + d_y[(size_t)s1 * H + n];
}

// ===================== launch =====================
extern "C" void kernel_launch(void* const* d_in, const int* in_sizes, int n_in,
                              void* d_out, int out_size)
{
    const float* x   = (const float*)d_in[0];   // [2,1024,1024]
    const float* gw  = (const float*)d_in[1];   // [8,1024]
    const float* wgu = (const float*)d_in[2];   // [8,1024,7168]
    const float* wdn = (const float*)d_in[3];   // [8,3584,1024]
    float* out = (float*)d_out;

    int write_logits = (out_size >= T * H + T * NE) ? 1 : 0;
    float* logits = out + (size_t)T * H;

    cudaFuncSetAttribute(moe_gemm_mma<H, true>,
                         cudaFuncAttributeMaxDynamicSharedMemorySize, SMEMSZ);
    cudaFuncSetAttribute(moe_gemm_mma<FF, false>,
                         cudaFuncAttributeMaxDynamicSharedMemorySize, SMEMSZ);

    zero_counts_kernel<<<1, 32>>>();
    router_kernel<<<(T * 32 + 255) / 256, 256>>>(x, gw, logits, write_logits);
    scan_kernel<<<1, 1>>>();
    scatter_kernel<<<(T + 255) / 256, 256>>>();
    moe_gemm_mma<H, true><<<dim3(16, FF / 64, NE), 256, SMEMSZ>>>(x, wgu);      // (16, 56, 8)
    moe_gemm_mma<FF, false><<<dim3(16, H / 128, NE), 256, SMEMSZ>>>(nullptr, wdn); // (16, 8, 8)
    combine_kernel<<<(T * H + 255) / 256, 256>>>(out);
}